// round 4
// baseline (speedup 1.0000x reference)
#include <cuda_runtime.h>
#include <cuda_bf16.h>

#define N_NODES 50000
#define N_EDGES 800000
#define F0      128
#define H       64
#define NB      512
#define KTOP    30
#define CCH     32
#define LOUT    26      // KTOP - 5 + 1
#define FC1_IN  832     // 32*26
#define MAXN    1024

// ---------------- scratch (device globals; no allocation) ----------------
__device__ float g_agg[N_NODES * F0];          // reused (64-wide for layers 2/3)
__device__ float g_h1[N_NODES * H];
__device__ float g_h2[N_NODES * H];
__device__ int   g_deg[N_NODES];
__device__ int   g_cnt[NB];
__device__ int   g_start[NB];
__device__ float g_pool[NB * KTOP * H];
__device__ float g_conv[NB * FC1_IN];

// ---------------- zero kernels ----------------
__global__ void zero_agg_k(int n) {
    int i = blockIdx.x * blockDim.x + threadIdx.x;
    if (i < n) g_agg[i] = 0.f;
}
__global__ void zero_deg_cnt_k() {
    int i = blockIdx.x * blockDim.x + threadIdx.x;
    if (i < N_NODES) g_deg[i] = 0;
    if (i < NB) g_cnt[i] = 0;
}
__global__ void zero_pool_k() {
    int i = blockIdx.x * blockDim.x + threadIdx.x;
    if (i < NB * KTOP * H) g_pool[i] = 0.f;
}

// ---------------- degree + counts (indices are int32!) ----------------
__global__ void deg_k(const int* __restrict__ dst) {
    int e = blockIdx.x * blockDim.x + threadIdx.x;
    if (e < N_EDGES) atomicAdd(&g_deg[dst[e]], 1);
}
__global__ void cnt_k(const int* __restrict__ batch) {
    int i = blockIdx.x * blockDim.x + threadIdx.x;
    if (i < N_NODES) atomicAdd(&g_cnt[batch[i]], 1);
}
__global__ void scan_k() {
    __shared__ int s[NB];
    int t = threadIdx.x;
    s[t] = g_cnt[t];
    __syncthreads();
    for (int off = 1; off < NB; off <<= 1) {
        int v = (t >= off) ? s[t - off] : 0;
        __syncthreads();
        s[t] += v;
        __syncthreads();
    }
    g_start[t] = s[t] - g_cnt[t];
}

// ---------------- edge scatter: agg[dst] += x[src] ----------------
template <int F>
__global__ void scatter_k(const int* __restrict__ src,
                          const int* __restrict__ dst,
                          const float* __restrict__ xin) {
    const int per = F / 4;                 // float4 chunks per edge
    long long tid = (long long)blockIdx.x * blockDim.x + threadIdx.x;
    long long total = (long long)N_EDGES * per;
    if (tid >= total) return;
    int e = (int)(tid / per);
    int c = (int)(tid % per) * 4;
    int s = src[e];
    int d = dst[e];
    float4 v = *(const float4*)(xin + (long long)s * F + c);
    float* o = g_agg + (long long)d * F + c;
    atomicAdd(o + 0, v.x);
    atomicAdd(o + 1, v.y);
    atomicAdd(o + 2, v.z);
    atomicAdd(o + 3, v.w);
}

// ---------------- SAGE: out = relu((agg/deg)@Wl + b + x@Wr) ----------------
template <int F, int NPB>
__global__ void sage_k(const float* __restrict__ xin,
                       const float* __restrict__ Wl,
                       const float* __restrict__ bias,
                       const float* __restrict__ Wr,
                       float* __restrict__ out) {
    __shared__ float sa[NPB][F];
    __shared__ float sx[NPB][F];
    int ty = threadIdx.y;
    int node = blockIdx.x * NPB + ty;
    if (node < N_NODES) {
        float dinv = 1.f / fmaxf((float)g_deg[node], 1.f);
        for (int k = threadIdx.x; k < F; k += H) {
            sa[ty][k] = g_agg[(long long)node * F + k] * dinv;
            sx[ty][k] = xin[(long long)node * F + k];
        }
    }
    __syncthreads();
    if (node < N_NODES) {
        int j = threadIdx.x;
        float acc = bias[j];
#pragma unroll 8
        for (int k = 0; k < F; k++)
            acc = fmaf(sa[ty][k], Wl[k * H + j], fmaf(sx[ty][k], Wr[k * H + j], acc));
        out[(long long)node * H + j] = fmaxf(acc, 0.f);
    }
}

// ---------------- sort-pool: stable top-K by last channel desc ----------------
__global__ void sortpool_k(const float* __restrict__ h) {
    int g = blockIdx.x;
    int tid = threadIdx.x;
    int s0 = g_start[g], n = g_cnt[g];
    __shared__ float v[MAXN];
    __shared__ int sel[KTOP];
    bool fits = (n <= MAXN);
    if (fits)
        for (int i = tid; i < n; i += blockDim.x)
            v[i] = h[(long long)(s0 + i) * H + (H - 1)];
    __syncthreads();
    for (int i = tid; i < n; i += blockDim.x) {
        float vi = fits ? v[i] : h[(long long)(s0 + i) * H + (H - 1)];
        int r = 0;
        for (int j = 0; j < n; j++) {
            float vj = fits ? v[j] : h[(long long)(s0 + j) * H + (H - 1)];
            r += (vj > vi) || (vj == vi && j < i);
            if (r >= KTOP) break;
        }
        if (r < KTOP) sel[r] = s0 + i;
    }
    __syncthreads();
    int m = n < KTOP ? n : KTOP;
    for (int idx = tid; idx < m * H; idx += blockDim.x) {
        int r = idx >> 6, c = idx & 63;
        g_pool[((long long)g * KTOP + r) * H + c] = h[(long long)sel[r] * H + c];
    }
}

// ---------------- conv1d (NCH, OIH, VALID, kernel=5) + relu ----------------
__global__ void conv_k(const float* __restrict__ convw,
                       const float* __restrict__ convb) {
    int g = blockIdx.x;
    int tid = threadIdx.x;
    __shared__ float p[KTOP * H];          // [t][i]
    for (int i = tid; i < KTOP * H; i += blockDim.x)
        p[i] = g_pool[(long long)g * KTOP * H + i];
    __syncthreads();
    for (int idx = tid; idx < CCH * LOUT; idx += blockDim.x) {
        int o = idx & 31;                  // warp spans o -> p access broadcast
        int t = idx >> 5;
        float acc = convb[o];
        const float* w = convw + o * (H * 5);
#pragma unroll 4
        for (int i = 0; i < H; i++) {
#pragma unroll
            for (int hh = 0; hh < 5; hh++)
                acc = fmaf(p[(t + hh) * H + i], w[i * 5 + hh], acc);
        }
        g_conv[(long long)g * FC1_IN + o * LOUT + t] = fmaxf(acc, 0.f);
    }
}

// ---------------- FC1 + relu, FC2, log_softmax ----------------
__global__ void fc_k(const float* __restrict__ w1, const float* __restrict__ b1v,
                     const float* __restrict__ w2, const float* __restrict__ b2v,
                     float* __restrict__ out) {
    int g = blockIdx.x;
    int t = threadIdx.x;                   // 64 threads
    __shared__ float c[FC1_IN];
    __shared__ float f[H];
    __shared__ float logits[10];
    for (int i = t; i < FC1_IN; i += H) c[i] = g_conv[(long long)g * FC1_IN + i];
    __syncthreads();
    float acc = b1v[t];
    for (int k = 0; k < FC1_IN; k++) acc = fmaf(c[k], w1[k * H + t], acc);
    f[t] = fmaxf(acc, 0.f);
    __syncthreads();
    if (t < 10) {
        float a = b2v[t];
#pragma unroll
        for (int k = 0; k < H; k++) a = fmaf(f[k], w2[k * 10 + t], a);
        logits[t] = a;
    }
    __syncthreads();
    if (t == 0) {
        float mx = -1e30f;
        for (int i = 0; i < 10; i++) mx = fmaxf(mx, logits[i]);
        float s = 0.f;
        for (int i = 0; i < 10; i++) s += expf(logits[i] - mx);
        float ls = logf(s) + mx;
        for (int i = 0; i < 10; i++) out[g * 10 + i] = logits[i] - ls;
    }
}

extern "C" void kernel_launch(void* const* d_in, const int* in_sizes, int n_in,
                              void* d_out, int out_size) {
    const float* x     = (const float*)d_in[0];
    const int*   ei    = (const int*)d_in[1];      // int32 (JAX x64 disabled)
    const int*   batch = (const int*)d_in[2];      // int32
    const float* W1l = (const float*)d_in[3];
    const float* b1  = (const float*)d_in[4];
    const float* W1r = (const float*)d_in[5];
    const float* W2l = (const float*)d_in[6];
    const float* b2  = (const float*)d_in[7];
    const float* W2r = (const float*)d_in[8];
    const float* W3l = (const float*)d_in[9];
    const float* b3  = (const float*)d_in[10];
    const float* W3r = (const float*)d_in[11];
    const float* convw = (const float*)d_in[12];
    const float* convb = (const float*)d_in[13];
    const float* lin1w = (const float*)d_in[14];
    const float* lin1b = (const float*)d_in[15];
    const float* lin2w = (const float*)d_in[16];
    const float* lin2b = (const float*)d_in[17];
    const int* src = ei;
    const int* dst = ei + N_EDGES;
    float* out = (float*)d_out;

    // degrees + graph counts (shared across layers)
    zero_deg_cnt_k<<<(N_NODES + 255) / 256, 256>>>();
    deg_k<<<(N_EDGES + 255) / 256, 256>>>(dst);
    cnt_k<<<(N_NODES + 255) / 256, 256>>>(batch);
    scan_k<<<1, NB>>>();

    // ---- layer 1 (F=128) ----
    zero_agg_k<<<(N_NODES * F0 + 255) / 256, 256>>>(N_NODES * F0);
    {
        long long tot = (long long)N_EDGES * (F0 / 4);
        scatter_k<F0><<<(int)((tot + 255) / 256), 256>>>(src, dst, x);
    }
    sage_k<F0, 4><<<(N_NODES + 3) / 4, dim3(H, 4)>>>(x, W1l, b1, W1r, g_h1);

    // ---- layer 2 (F=64) ----
    zero_agg_k<<<(N_NODES * H + 255) / 256, 256>>>(N_NODES * H);
    {
        long long tot = (long long)N_EDGES * (H / 4);
        scatter_k<H><<<(int)((tot + 255) / 256), 256>>>(src, dst, g_h1);
    }
    sage_k<H, 4><<<(N_NODES + 3) / 4, dim3(H, 4)>>>(g_h1, W2l, b2, W2r, g_h2);

    // ---- layer 3 (F=64) ----
    zero_agg_k<<<(N_NODES * H + 255) / 256, 256>>>(N_NODES * H);
    {
        long long tot = (long long)N_EDGES * (H / 4);
        scatter_k<H><<<(int)((tot + 255) / 256), 256>>>(src, dst, g_h2);
    }
    sage_k<H, 4><<<(N_NODES + 3) / 4, dim3(H, 4)>>>(g_h2, W3l, b3, W3r, g_h1);

    // ---- sort-pool ----
    zero_pool_k<<<(NB * KTOP * H + 255) / 256, 256>>>();
    sortpool_k<<<NB, 128>>>(g_h1);

    // ---- conv + mlp + log_softmax ----
    conv_k<<<NB, 256>>>(convw, convb);
    fc_k<<<NB, H>>>(lin1w, lin1b, lin2w, lin2b, out);
}

// round 6
// speedup vs baseline: 3.9498x; 3.9498x over previous
#include <cuda_runtime.h>
#include <cuda_bf16.h>

#define N_NODES 50000
#define N_EDGES 800000
#define F0      128
#define H       64
#define NB      512
#define KTOP    30
#define CCH     32
#define LOUT    26      // KTOP - 5 + 1
#define FC1_IN  832     // 32*26
#define MAXN    1024

// ---------------- scratch (device globals; no allocation) ----------------
__device__ __align__(256) float g_C[N_NODES * 128];     // GEMM out: [ h@Wl | h@Wr ]
__device__ __align__(256) float g_h1[N_NODES * H];
__device__ __align__(256) float g_h2[N_NODES * H];
__device__ __align__(256) float g_wcat[3][F0 * 128];    // per-layer [Wl|Wr], K-major
__device__ int   g_deg[N_NODES];
__device__ int   g_rowstart[N_NODES];
__device__ int   g_cursor[N_NODES];
__device__ int   g_csr[N_EDGES];
__device__ int   g_cnt[NB];
__device__ int   g_start[NB];
__device__ __align__(256) float g_pool[NB * KTOP * H];
__device__ __align__(256) float g_conv[NB * FC1_IN];

// ---------------- init / counting ----------------
__global__ void zero_deg_cnt_k() {
    int i = blockIdx.x * blockDim.x + threadIdx.x;
    if (i < N_NODES) g_deg[i] = 0;
    if (i < NB) g_cnt[i] = 0;
}
__global__ void zero_pool_k() {
    int i = blockIdx.x * blockDim.x + threadIdx.x;
    if (i < NB * KTOP * H) g_pool[i] = 0.f;
}
__global__ void deg_k(const int* __restrict__ dst) {
    int e = blockIdx.x * blockDim.x + threadIdx.x;
    if (e < N_EDGES) atomicAdd(&g_deg[dst[e]], 1);
}
__global__ void cnt_k(const int* __restrict__ batch) {
    int i = blockIdx.x * blockDim.x + threadIdx.x;
    if (i < N_NODES) atomicAdd(&g_cnt[batch[i]], 1);
}
__global__ void scan_k() {   // graph starts (batch is sorted)
    __shared__ int s[NB];
    int t = threadIdx.x;
    s[t] = g_cnt[t];
    __syncthreads();
    for (int off = 1; off < NB; off <<= 1) {
        int v = (t >= off) ? s[t - off] : 0;
        __syncthreads();
        s[t] += v;
        __syncthreads();
    }
    g_start[t] = s[t] - g_cnt[t];
}

// exclusive scan of g_deg -> g_rowstart / g_cursor. one block, 1024 threads.
#define SCAN_CH 49
__global__ void nodescan_k() {
    __shared__ int s[1024];
    int t = threadIdx.x;
    int base = t * SCAN_CH;
    int loc[SCAN_CH];
    int sum = 0;
#pragma unroll
    for (int i = 0; i < SCAN_CH; i++) {
        int idx = base + i;
        int v = (idx < N_NODES) ? g_deg[idx] : 0;
        loc[i] = sum;
        sum += v;
    }
    s[t] = sum;
    __syncthreads();
    for (int off = 1; off < 1024; off <<= 1) {
        int v = (t >= off) ? s[t - off] : 0;
        __syncthreads();
        s[t] += v;
        __syncthreads();
    }
    int offset = (t > 0) ? s[t - 1] : 0;
#pragma unroll
    for (int i = 0; i < SCAN_CH; i++) {
        int idx = base + i;
        if (idx < N_NODES) {
            g_rowstart[idx] = offset + loc[i];
            g_cursor[idx]   = offset + loc[i];
        }
    }
}
__global__ void fillcsr_k(const int* __restrict__ src, const int* __restrict__ dst) {
    int e = blockIdx.x * blockDim.x + threadIdx.x;
    if (e < N_EDGES) {
        int pos = atomicAdd(&g_cursor[dst[e]], 1);
        g_csr[pos] = src[e];
    }
}

// build [Wl | Wr] (K x 128, row-major) per layer
__global__ void wcat_k(const float* __restrict__ Wl, const float* __restrict__ Wr,
                       float* __restrict__ Wc, int K) {
    int i = blockIdx.x * blockDim.x + threadIdx.x;
    if (i < K * 64) {
        int k = i >> 6, j = i & 63;
        Wc[k * 128 + j]      = Wl[i];
        Wc[k * 128 + 64 + j] = Wr[i];
    }
}

// ---------------- tiled GEMM: C[M x 128] = A[M x K] @ B[K x 128] ----------------
template <int K>
__global__ __launch_bounds__(256) void gemm_k(const float* __restrict__ A,
                                              const float* __restrict__ B,
                                              float* __restrict__ C) {
    const int MT = 128, NT = 128, KT = 32;
    __shared__ float sA[MT][KT + 4];   // [m][k], padded (16B-aligned rows)
    __shared__ float sB[KT][NT];       // [k][n]
    int t = threadIdx.x;
    int m0 = blockIdx.x * MT;
    int ty = t >> 4, tx = t & 15;      // 16x16 thread grid, 8x8 micro-tile
    float acc[8][8];
#pragma unroll
    for (int i = 0; i < 8; i++)
#pragma unroll
        for (int j = 0; j < 8; j++) acc[i][j] = 0.f;

    for (int kk = 0; kk < K; kk += KT) {
#pragma unroll
        for (int i = 0; i < 4; i++) {           // A tile: 128 x 32
            int lin = t + i * 256;              // 0..1023
            int row = lin >> 3;
            int c4  = lin & 7;
            int grow = m0 + row;
            float4 v = make_float4(0.f, 0.f, 0.f, 0.f);
            if (grow < N_NODES)
                v = *(const float4*)(A + (long long)grow * K + kk + c4 * 4);
            *(float4*)&sA[row][c4 * 4] = v;
        }
#pragma unroll
        for (int i = 0; i < 4; i++) {           // B tile: 32 x 128
            int lin = t + i * 256;
            int row = lin >> 5;
            int c4  = lin & 31;
            *(float4*)&sB[row][c4 * 4] = *(const float4*)(B + (row + kk) * 128 + c4 * 4);
        }
        __syncthreads();
#pragma unroll
        for (int k = 0; k < KT; k++) {
            float a[8], b[8];
#pragma unroll
            for (int i = 0; i < 8; i++) a[i] = sA[ty * 8 + i][k];
            float4 b0 = *(float4*)&sB[k][tx * 8];
            float4 b1 = *(float4*)&sB[k][tx * 8 + 4];
            b[0] = b0.x; b[1] = b0.y; b[2] = b0.z; b[3] = b0.w;
            b[4] = b1.x; b[5] = b1.y; b[6] = b1.z; b[7] = b1.w;
#pragma unroll
            for (int i = 0; i < 8; i++)
#pragma unroll
                for (int j = 0; j < 8; j++)
                    acc[i][j] = fmaf(a[i], b[j], acc[i][j]);
        }
        __syncthreads();
    }
#pragma unroll
    for (int i = 0; i < 8; i++) {
        int grow = m0 + ty * 8 + i;
        if (grow < N_NODES) {
            float4 v0 = make_float4(acc[i][0], acc[i][1], acc[i][2], acc[i][3]);
            float4 v1 = make_float4(acc[i][4], acc[i][5], acc[i][6], acc[i][7]);
            *(float4*)(C + (long long)grow * 128 + tx * 8)     = v0;
            *(float4*)(C + (long long)grow * 128 + tx * 8 + 4) = v1;
        }
    }
}

// ---------------- gather: out = relu( mean_{j in N(i)} C[j,:64] + C[i,64:] + b ) ----------------
__global__ void gather_k(const float* __restrict__ C, const float* __restrict__ bias,
                         float* __restrict__ out) {
    int node = blockIdx.x * 4 + threadIdx.y;
    if (node >= N_NODES) return;
    int f = threadIdx.x;                        // 0..63
    int s = g_rowstart[node];
    int d = g_deg[node];
    float acc = 0.f;
    int e = 0;
    for (; e + 1 < d; e += 2) {
        int j0 = g_csr[s + e];
        int j1 = g_csr[s + e + 1];
        acc += C[(long long)j0 * 128 + f] + C[(long long)j1 * 128 + f];
    }
    if (e < d) acc += C[(long long)g_csr[s + e] * 128 + f];
    float dinv = 1.f / fmaxf((float)d, 1.f);
    float r = acc * dinv + C[(long long)node * 128 + 64 + f] + bias[f];
    out[(long long)node * H + f] = fmaxf(r, 0.f);
}

// ---------------- sort-pool: stable top-K by last channel desc ----------------
__global__ void sortpool_k(const float* __restrict__ h) {
    int g = blockIdx.x;
    int tid = threadIdx.x;
    int s0 = g_start[g], n = g_cnt[g];
    __shared__ float v[MAXN];
    __shared__ int sel[KTOP];
    bool fits = (n <= MAXN);
    if (fits)
        for (int i = tid; i < n; i += blockDim.x)
            v[i] = h[(long long)(s0 + i) * H + (H - 1)];
    __syncthreads();
    for (int i = tid; i < n; i += blockDim.x) {
        float vi = fits ? v[i] : h[(long long)(s0 + i) * H + (H - 1)];
        int r = 0;
        for (int j = 0; j < n; j++) {
            float vj = fits ? v[j] : h[(long long)(s0 + j) * H + (H - 1)];
            r += (vj > vi) || (vj == vi && j < i);
            if (r >= KTOP) break;
        }
        if (r < KTOP) sel[r] = s0 + i;
    }
    __syncthreads();
    int m = n < KTOP ? n : KTOP;
    for (int idx = tid; idx < m * H; idx += blockDim.x) {
        int r = idx >> 6, c = idx & 63;
        g_pool[((long long)g * KTOP + r) * H + c] = h[(long long)sel[r] * H + c];
    }
}

// ---------------- conv1d (NCH, OIH, VALID, kernel=5) + relu ----------------
__global__ void conv_k(const float* __restrict__ convw,
                       const float* __restrict__ convb) {
    int g = blockIdx.x;
    int tid = threadIdx.x;
    __shared__ float p[KTOP * H];          // [t][i]
    for (int i = tid; i < KTOP * H; i += blockDim.x)
        p[i] = g_pool[(long long)g * KTOP * H + i];
    __syncthreads();
    for (int idx = tid; idx < CCH * LOUT; idx += blockDim.x) {
        int o = idx & 31;
        int t = idx >> 5;
        float acc = convb[o];
        const float* w = convw + o * (H * 5);
#pragma unroll 4
        for (int i = 0; i < H; i++) {
#pragma unroll
            for (int hh = 0; hh < 5; hh++)
                acc = fmaf(p[(t + hh) * H + i], w[i * 5 + hh], acc);
        }
        g_conv[(long long)g * FC1_IN + o * LOUT + t] = fmaxf(acc, 0.f);
    }
}

// ---------------- FC1 + relu, FC2, log_softmax ----------------
__global__ void fc_k(const float* __restrict__ w1, const float* __restrict__ b1v,
                     const float* __restrict__ w2, const float* __restrict__ b2v,
                     float* __restrict__ out) {
    int g = blockIdx.x;
    int t = threadIdx.x;                   // 64 threads
    __shared__ float c[FC1_IN];
    __shared__ float f[H];
    __shared__ float logits[10];
    for (int i = t; i < FC1_IN; i += H) c[i] = g_conv[(long long)g * FC1_IN + i];
    __syncthreads();
    float acc = b1v[t];
    for (int k = 0; k < FC1_IN; k++) acc = fmaf(c[k], w1[k * H + t], acc);
    f[t] = fmaxf(acc, 0.f);
    __syncthreads();
    if (t < 10) {
        float a = b2v[t];
#pragma unroll
        for (int k = 0; k < H; k++) a = fmaf(f[k], w2[k * 10 + t], a);
        logits[t] = a;
    }
    __syncthreads();
    if (t == 0) {
        float mx = -1e30f;
        for (int i = 0; i < 10; i++) mx = fmaxf(mx, logits[i]);
        float s = 0.f;
        for (int i = 0; i < 10; i++) s += expf(logits[i] - mx);
        float ls = logf(s) + mx;
        for (int i = 0; i < 10; i++) out[g * 10 + i] = logits[i] - ls;
    }
}

extern "C" void kernel_launch(void* const* d_in, const int* in_sizes, int n_in,
                              void* d_out, int out_size) {
    const float* x     = (const float*)d_in[0];
    const int*   ei    = (const int*)d_in[1];      // int32 (JAX x64 disabled)
    const int*   batch = (const int*)d_in[2];      // int32
    const float* W1l = (const float*)d_in[3];
    const float* b1  = (const float*)d_in[4];
    const float* W1r = (const float*)d_in[5];
    const float* W2l = (const float*)d_in[6];
    const float* b2  = (const float*)d_in[7];
    const float* W2r = (const float*)d_in[8];
    const float* W3l = (const float*)d_in[9];
    const float* b3  = (const float*)d_in[10];
    const float* W3r = (const float*)d_in[11];
    const float* convw = (const float*)d_in[12];
    const float* convb = (const float*)d_in[13];
    const float* lin1w = (const float*)d_in[14];
    const float* lin1b = (const float*)d_in[15];
    const float* lin2w = (const float*)d_in[16];
    const float* lin2b = (const float*)d_in[17];
    const int* src = ei;
    const int* dst = ei + N_EDGES;
    float* out = (float*)d_out;

    float* wc0;  cudaGetSymbolAddress((void**)&wc0, g_wcat);
    float* wc1 = wc0 + F0 * 128;
    float* wc2 = wc0 + 2 * F0 * 128;
    float* Cbuf; cudaGetSymbolAddress((void**)&Cbuf, g_C);
    float* h1;   cudaGetSymbolAddress((void**)&h1, g_h1);
    float* h2;   cudaGetSymbolAddress((void**)&h2, g_h2);

    // ---- CSR build + graph offsets ----
    zero_deg_cnt_k<<<(N_NODES + 255) / 256, 256>>>();
    deg_k<<<(N_EDGES + 255) / 256, 256>>>(dst);
    cnt_k<<<(N_NODES + 255) / 256, 256>>>(batch);
    scan_k<<<1, NB>>>();
    nodescan_k<<<1, 1024>>>();
    fillcsr_k<<<(N_EDGES + 255) / 256, 256>>>(src, dst);

    // ---- concat weights ----
    wcat_k<<<(F0 * 64 + 255) / 256, 256>>>(W1l, W1r, wc0, F0);
    wcat_k<<<(H * 64 + 255) / 256, 256>>>(W2l, W2r, wc1, H);
    wcat_k<<<(H * 64 + 255) / 256, 256>>>(W3l, W3r, wc2, H);

    const int GB = (N_NODES + 127) / 128;          // gemm blocks
    const int AB = (N_NODES + 3) / 4;              // gather blocks

    // ---- layer 1 ----
    gemm_k<F0><<<GB, 256>>>(x, wc0, Cbuf);
    gather_k<<<AB, dim3(64, 4)>>>(Cbuf, b1, h1);
    // ---- layer 2 ----
    gemm_k<H><<<GB, 256>>>(h1, wc1, Cbuf);
    gather_k<<<AB, dim3(64, 4)>>>(Cbuf, b2, h2);
    // ---- layer 3 ----
    gemm_k<H><<<GB, 256>>>(h2, wc2, Cbuf);
    gather_k<<<AB, dim3(64, 4)>>>(Cbuf, b3, h1);

    // ---- sort-pool ----
    zero_pool_k<<<(NB * KTOP * H + 255) / 256, 256>>>();
    sortpool_k<<<NB, 128>>>(h1);

    // ---- conv + mlp + log_softmax ----
    conv_k<<<NB, 256>>>(convw, convb);
    fc_k<<<NB, H>>>(lin1w, lin1b, lin2w, lin2b, out);
}

// round 7
// speedup vs baseline: 12.0151x; 3.0420x over previous
#include <cuda_runtime.h>
#include <cuda_bf16.h>

#define N_NODES 50000
#define N_EDGES 800000
#define F0      128
#define H       64
#define NB      512
#define KTOP    30
#define CCH     32
#define LOUT    26      // KTOP - 5 + 1
#define FC1_IN  832     // 32*26
#define MAXN    1024
#define SCB     196     // scan blocks: 196*256 >= 50000

// ---------------- scratch (device globals; no allocation) ----------------
__device__ __align__(256) float g_C[N_NODES * 128];     // GEMM out: [ h@Wl | h@Wr ]
__device__ __align__(256) float g_h1[N_NODES * H];
__device__ __align__(256) float g_h2[N_NODES * H];
__device__ __align__(256) float g_wcat[3][F0 * 128];    // per-layer [Wl|Wr], K-major
__device__ int   g_deg[N_NODES];
__device__ int   g_rowstart[N_NODES];
__device__ int   g_cursor[N_NODES];
__device__ int   g_csr[N_EDGES];
__device__ int   g_cnt[NB];
__device__ int   g_start[NB];
__device__ int   g_bsum[SCB];
__device__ int   g_boff[SCB];
__device__ __align__(256) float g_pool[NB * KTOP * H];
__device__ __align__(256) float g_conv[NB * FC1_IN];

// ---------------- init / counting ----------------
__global__ void zero_deg_cnt_k() {
    int i = blockIdx.x * blockDim.x + threadIdx.x;
    if (i < N_NODES) g_deg[i] = 0;
    if (i < NB) g_cnt[i] = 0;
}
// degrees (over edges) + per-graph counts (over nodes) in one kernel
__global__ void count_k(const int* __restrict__ dst, const int* __restrict__ batch) {
    int e = blockIdx.x * blockDim.x + threadIdx.x;
    if (e < N_EDGES) atomicAdd(&g_deg[dst[e]], 1);
    if (e < N_NODES) atomicAdd(&g_cnt[batch[e]], 1);
}
// graph starts (batch is sorted)
__global__ void scan_k() {
    __shared__ int s[NB];
    int t = threadIdx.x;
    s[t] = g_cnt[t];
    __syncthreads();
    for (int off = 1; off < NB; off <<= 1) {
        int v = (t >= off) ? s[t - off] : 0;
        __syncthreads();
        s[t] += v;
        __syncthreads();
    }
    g_start[t] = s[t] - g_cnt[t];
}

// ---------------- 3-stage coalesced exclusive scan of g_deg ----------------
__global__ void scanA_k() {            // per-block sums
    __shared__ int s[256];
    int b = blockIdx.x, t = threadIdx.x;
    int idx = b * 256 + t;
    int v = (idx < N_NODES) ? g_deg[idx] : 0;
    s[t] = v;
    __syncthreads();
    for (int off = 1; off < 256; off <<= 1) {
        int u = (t >= off) ? s[t - off] : 0;
        __syncthreads();
        s[t] += u;
        __syncthreads();
    }
    if (t == 255) g_bsum[b] = s[255];
}
__global__ void scanB_k() {            // scan the 196 block sums (one block, 256 thr)
    __shared__ int s[256];
    int t = threadIdx.x;
    s[t] = (t < SCB) ? g_bsum[t] : 0;
    __syncthreads();
    for (int off = 1; off < 256; off <<= 1) {
        int u = (t >= off) ? s[t - off] : 0;
        __syncthreads();
        s[t] += u;
        __syncthreads();
    }
    if (t < SCB) g_boff[t] = s[t] - g_bsum[t];   // exclusive
}
__global__ void scanC_k() {            // finalize rowstart / cursor
    __shared__ int s[256];
    int b = blockIdx.x, t = threadIdx.x;
    int idx = b * 256 + t;
    int v = (idx < N_NODES) ? g_deg[idx] : 0;
    s[t] = v;
    __syncthreads();
    for (int off = 1; off < 256; off <<= 1) {
        int u = (t >= off) ? s[t - off] : 0;
        __syncthreads();
        s[t] += u;
        __syncthreads();
    }
    if (idx < N_NODES) {
        int ex = g_boff[b] + s[t] - v;
        g_rowstart[idx] = ex;
        g_cursor[idx]   = ex;
    }
}
__global__ void fillcsr_k(const int* __restrict__ src, const int* __restrict__ dst) {
    int e = blockIdx.x * blockDim.x + threadIdx.x;
    if (e < N_EDGES) {
        int pos = atomicAdd(&g_cursor[dst[e]], 1);
        g_csr[pos] = src[e];
    }
}

// ---------------- build [Wl | Wr] for all 3 layers in one kernel ----------------
__global__ void wcat_all_k(const float* __restrict__ W1l, const float* __restrict__ W1r,
                           const float* __restrict__ W2l, const float* __restrict__ W2r,
                           const float* __restrict__ W3l, const float* __restrict__ W3r) {
    int i = blockIdx.x * blockDim.x + threadIdx.x;   // 0 .. 16383
    if (i < F0 * 64) {                                // layer 1: K=128
        int k = i >> 6, j = i & 63;
        g_wcat[0][k * 128 + j]      = W1l[i];
        g_wcat[0][k * 128 + 64 + j] = W1r[i];
    } else if (i < F0 * 64 + H * 64) {                // layer 2
        int p = i - F0 * 64;
        int k = p >> 6, j = p & 63;
        g_wcat[1][k * 128 + j]      = W2l[p];
        g_wcat[1][k * 128 + 64 + j] = W2r[p];
    } else if (i < F0 * 64 + 2 * H * 64) {            // layer 3
        int p = i - F0 * 64 - H * 64;
        int k = p >> 6, j = p & 63;
        g_wcat[2][k * 128 + j]      = W3l[p];
        g_wcat[2][k * 128 + 64 + j] = W3r[p];
    }
}

// ---------------- tiled GEMM: C[M x 128] = A[M x K] @ B[K x 128] ----------------
template <int K>
__global__ __launch_bounds__(256) void gemm_k(const float* __restrict__ A,
                                              const float* __restrict__ B,
                                              float* __restrict__ C) {
    const int MT = 128, NT = 128, KT = 32;
    __shared__ float sA[MT][KT + 4];   // [m][k], padded
    __shared__ float sB[KT][NT];       // [k][n]
    int t = threadIdx.x;
    int m0 = blockIdx.x * MT;
    int ty = t >> 4, tx = t & 15;      // 16x16 thread grid, 8x8 micro-tile
    float acc[8][8];
#pragma unroll
    for (int i = 0; i < 8; i++)
#pragma unroll
        for (int j = 0; j < 8; j++) acc[i][j] = 0.f;

    for (int kk = 0; kk < K; kk += KT) {
#pragma unroll
        for (int i = 0; i < 4; i++) {           // A tile: 128 x 32
            int lin = t + i * 256;
            int row = lin >> 3;
            int c4  = lin & 7;
            int grow = m0 + row;
            float4 v = make_float4(0.f, 0.f, 0.f, 0.f);
            if (grow < N_NODES)
                v = *(const float4*)(A + (long long)grow * K + kk + c4 * 4);
            *(float4*)&sA[row][c4 * 4] = v;
        }
#pragma unroll
        for (int i = 0; i < 4; i++) {           // B tile: 32 x 128
            int lin = t + i * 256;
            int row = lin >> 5;
            int c4  = lin & 31;
            *(float4*)&sB[row][c4 * 4] = *(const float4*)(B + (row + kk) * 128 + c4 * 4);
        }
        __syncthreads();
#pragma unroll
        for (int k = 0; k < KT; k++) {
            float a[8], b[8];
#pragma unroll
            for (int i = 0; i < 8; i++) a[i] = sA[ty * 8 + i][k];
            float4 b0 = *(float4*)&sB[k][tx * 8];
            float4 b1 = *(float4*)&sB[k][tx * 8 + 4];
            b[0] = b0.x; b[1] = b0.y; b[2] = b0.z; b[3] = b0.w;
            b[4] = b1.x; b[5] = b1.y; b[6] = b1.z; b[7] = b1.w;
#pragma unroll
            for (int i = 0; i < 8; i++)
#pragma unroll
                for (int j = 0; j < 8; j++)
                    acc[i][j] = fmaf(a[i], b[j], acc[i][j]);
        }
        __syncthreads();
    }
#pragma unroll
    for (int i = 0; i < 8; i++) {
        int grow = m0 + ty * 8 + i;
        if (grow < N_NODES) {
            float4 v0 = make_float4(acc[i][0], acc[i][1], acc[i][2], acc[i][3]);
            float4 v1 = make_float4(acc[i][4], acc[i][5], acc[i][6], acc[i][7]);
            *(float4*)(C + (long long)grow * 128 + tx * 8)     = v0;
            *(float4*)(C + (long long)grow * 128 + tx * 8 + 4) = v1;
        }
    }
}

// ---------------- gather: out = relu( mean_{j in N(i)} C[j,:64] + C[i,64:] + b ) ----
// 16 threads per node, float4 lanes; 8 nodes per 128-thread block.
__global__ void gather_k(const float4* __restrict__ C4, const float* __restrict__ bias,
                         float* __restrict__ out) {
    int node = blockIdx.x * 8 + (threadIdx.x >> 4);
    if (node >= N_NODES) return;
    int l = threadIdx.x & 15;                   // float4 lane (covers 64 floats)
    int s = g_rowstart[node];
    int d = g_deg[node];
    float4 acc = make_float4(0.f, 0.f, 0.f, 0.f);
    int e = 0;
    for (; e + 4 <= d; e += 4) {
        int j0 = g_csr[s + e];
        int j1 = g_csr[s + e + 1];
        int j2 = g_csr[s + e + 2];
        int j3 = g_csr[s + e + 3];
        float4 a = C4[(long long)j0 * 32 + l];
        float4 b = C4[(long long)j1 * 32 + l];
        float4 c = C4[(long long)j2 * 32 + l];
        float4 dd = C4[(long long)j3 * 32 + l];
        acc.x += a.x + b.x + c.x + dd.x;
        acc.y += a.y + b.y + c.y + dd.y;
        acc.z += a.z + b.z + c.z + dd.z;
        acc.w += a.w + b.w + c.w + dd.w;
    }
    for (; e < d; e++) {
        float4 a = C4[(long long)g_csr[s + e] * 32 + l];
        acc.x += a.x; acc.y += a.y; acc.z += a.z; acc.w += a.w;
    }
    float dinv = 1.f / fmaxf((float)d, 1.f);
    float4 self = C4[(long long)node * 32 + 16 + l];
    float4 bv = ((const float4*)bias)[l];
    float4 r;
    r.x = fmaxf(acc.x * dinv + self.x + bv.x, 0.f);
    r.y = fmaxf(acc.y * dinv + self.y + bv.y, 0.f);
    r.z = fmaxf(acc.z * dinv + self.z + bv.z, 0.f);
    r.w = fmaxf(acc.w * dinv + self.w + bv.w, 0.f);
    ((float4*)out)[(long long)node * 16 + l] = r;
}

// ---------------- sort-pool: stable top-K by last channel desc (zero-pad fused) ----
__global__ void sortpool_k(const float* __restrict__ h) {
    int g = blockIdx.x;
    int tid = threadIdx.x;
    int s0 = g_start[g], n = g_cnt[g];
    __shared__ float v[MAXN];
    __shared__ int sel[KTOP];
    bool fits = (n <= MAXN);
    if (fits)
        for (int i = tid; i < n; i += blockDim.x)
            v[i] = h[(long long)(s0 + i) * H + (H - 1)];
    __syncthreads();
    for (int i = tid; i < n; i += blockDim.x) {
        float vi = fits ? v[i] : h[(long long)(s0 + i) * H + (H - 1)];
        int r = 0;
        for (int j = 0; j < n; j++) {
            float vj = fits ? v[j] : h[(long long)(s0 + j) * H + (H - 1)];
            r += (vj > vi) || (vj == vi && j < i);
            if (r >= KTOP) break;
        }
        if (r < KTOP) sel[r] = s0 + i;
    }
    __syncthreads();
    int m = n < KTOP ? n : KTOP;
    for (int idx = tid; idx < KTOP * H; idx += blockDim.x) {
        int r = idx >> 6, c = idx & 63;
        float val = (r < m) ? h[(long long)sel[r] * H + c] : 0.f;
        g_pool[((long long)g * KTOP + r) * H + c] = val;
    }
}

// ---------------- conv1d (NCH, OIH, VALID, kernel=5) + relu ----------------
__global__ void conv_k(const float* __restrict__ convw,
                       const float* __restrict__ convb) {
    int g = blockIdx.x;
    int tid = threadIdx.x;
    __shared__ float p[KTOP * H];          // [t][i]
    __shared__ float sw[CCH * 321];        // padded: bank = (o + c) % 32
    for (int i = tid; i < KTOP * H; i += blockDim.x)
        p[i] = g_pool[(long long)g * KTOP * H + i];
    for (int i = tid; i < CCH * 320; i += blockDim.x) {
        int o = i / 320, c = i % 320;
        sw[o * 321 + c] = convw[i];
    }
    __syncthreads();
    for (int idx = tid; idx < CCH * LOUT; idx += blockDim.x) {
        int o = idx & 31;                  // lane = o -> sw conflict-free, p broadcast
        int t = idx >> 5;
        float acc = convb[o];
        const float* w = sw + o * 321;
#pragma unroll 4
        for (int i = 0; i < H; i++) {
#pragma unroll
            for (int hh = 0; hh < 5; hh++)
                acc = fmaf(p[(t + hh) * H + i], w[i * 5 + hh], acc);
        }
        g_conv[(long long)g * FC1_IN + o * LOUT + t] = fmaxf(acc, 0.f);
    }
}

// ---------------- FC1 + relu, FC2, log_softmax ----------------
__global__ void fc_k(const float* __restrict__ w1, const float* __restrict__ b1v,
                     const float* __restrict__ w2, const float* __restrict__ b2v,
                     float* __restrict__ out) {
    int g = blockIdx.x;
    int t = threadIdx.x;                   // 64 threads
    __shared__ float c[FC1_IN];
    __shared__ float f[H];
    __shared__ float logits[10];
    for (int i = t; i < FC1_IN; i += H) c[i] = g_conv[(long long)g * FC1_IN + i];
    __syncthreads();
    float acc = b1v[t];
#pragma unroll 8
    for (int k = 0; k < FC1_IN; k++) acc = fmaf(c[k], w1[k * H + t], acc);
    f[t] = fmaxf(acc, 0.f);
    __syncthreads();
    if (t < 10) {
        float a = b2v[t];
#pragma unroll
        for (int k = 0; k < H; k++) a = fmaf(f[k], w2[k * 10 + t], a);
        logits[t] = a;
    }
    __syncthreads();
    if (t == 0) {
        float mx = -1e30f;
        for (int i = 0; i < 10; i++) mx = fmaxf(mx, logits[i]);
        float s = 0.f;
        for (int i = 0; i < 10; i++) s += expf(logits[i] - mx);
        float ls = logf(s) + mx;
        for (int i = 0; i < 10; i++) out[g * 10 + i] = logits[i] - ls;
    }
}

extern "C" void kernel_launch(void* const* d_in, const int* in_sizes, int n_in,
                              void* d_out, int out_size) {
    const float* x     = (const float*)d_in[0];
    const int*   ei    = (const int*)d_in[1];      // int32 (JAX x64 disabled)
    const int*   batch = (const int*)d_in[2];      // int32
    const float* W1l = (const float*)d_in[3];
    const float* b1  = (const float*)d_in[4];
    const float* W1r = (const float*)d_in[5];
    const float* W2l = (const float*)d_in[6];
    const float* b2  = (const float*)d_in[7];
    const float* W2r = (const float*)d_in[8];
    const float* W3l = (const float*)d_in[9];
    const float* b3  = (const float*)d_in[10];
    const float* W3r = (const float*)d_in[11];
    const float* convw = (const float*)d_in[12];
    const float* convb = (const float*)d_in[13];
    const float* lin1w = (const float*)d_in[14];
    const float* lin1b = (const float*)d_in[15];
    const float* lin2w = (const float*)d_in[16];
    const float* lin2b = (const float*)d_in[17];
    const int* src = ei;
    const int* dst = ei + N_EDGES;
    float* out = (float*)d_out;

    float* wc0;  cudaGetSymbolAddress((void**)&wc0, g_wcat);
    float* wc1 = wc0 + F0 * 128;
    float* wc2 = wc0 + 2 * F0 * 128;
    float* Cbuf; cudaGetSymbolAddress((void**)&Cbuf, g_C);
    float* h1;   cudaGetSymbolAddress((void**)&h1, g_h1);
    float* h2;   cudaGetSymbolAddress((void**)&h2, g_h2);

    const int GB = (N_NODES + 127) / 128;          // gemm blocks
    const int AB = (N_NODES + 7) / 8;              // gather blocks

    // index 0..2
    zero_deg_cnt_k<<<(N_NODES + 255) / 256, 256>>>();
    count_k<<<(N_EDGES + 255) / 256, 256>>>(dst, batch);
    wcat_all_k<<<(F0 * 64 + 2 * H * 64 + 255) / 256, 256>>>(W1l, W1r, W2l, W2r, W3l, W3r);

    // index 3: profiled slot — layer-1 GEMM (only needs x + wcat)
    gemm_k<F0><<<GB, 256>>>(x, wc0, Cbuf);

    // index 4..8: CSR build + graph offsets
    scan_k<<<1, NB>>>();
    scanA_k<<<SCB, 256>>>();
    scanB_k<<<1, 256>>>();
    scanC_k<<<SCB, 256>>>();
    fillcsr_k<<<(N_EDGES + 255) / 256, 256>>>(src, dst);

    // ---- layer 1 aggregate, then layers 2/3 ----
    gather_k<<<AB, 128>>>((const float4*)Cbuf, b1, h1);
    gemm_k<H><<<GB, 256>>>(h1, wc1, Cbuf);
    gather_k<<<AB, 128>>>((const float4*)Cbuf, b2, h2);
    gemm_k<H><<<GB, 256>>>(h2, wc2, Cbuf);
    gather_k<<<AB, 128>>>((const float4*)Cbuf, b3, h1);

    // ---- sort-pool (zero-pad fused) ----
    sortpool_k<<<NB, 128>>>(h1);

    // ---- conv + mlp + log_softmax ----
    conv_k<<<NB, 256>>>(convw, convb);
    fc_k<<<NB, H>>>(lin1w, lin1b, lin2w, lin2b, out);
}

// round 10
// speedup vs baseline: 12.6309x; 1.0513x over previous
#include <cuda_runtime.h>
#include <cuda_bf16.h>

#define N_NODES 50000
#define N_EDGES 800000
#define F0      128
#define H       64
#define NB      512
#define KTOP    30
#define CCH     32
#define LOUT    26      // KTOP - 5 + 1
#define FC1_IN  832     // 32*26
#define MAXN    1024
#define SCB     196     // scan blocks: 196*256 >= 50000

// ---------------- scratch (device globals; no allocation) ----------------
__device__ __align__(256) float g_C[N_NODES * 128];     // GEMM out: [ h@Wl | h@Wr ]
__device__ __align__(256) float g_h1[N_NODES * H];
__device__ __align__(256) float g_h2[N_NODES * H];
__device__ __align__(256) float g_wcat[3][F0 * 128];    // per-layer [Wl|Wr], K-major
__device__ __align__(256) float g_w1t[H * FC1_IN];      // lin1w transposed [64][832]
__device__ int   g_deg[N_NODES];
__device__ int   g_rowstart[N_NODES];
__device__ int   g_cursor[N_NODES];
__device__ int   g_csr[N_EDGES];
__device__ int   g_cnt[NB];
__device__ int   g_start[NB];
__device__ int   g_bsum[SCB];
__device__ int   g_boff[SCB];
__device__ __align__(256) float g_pool[NB * KTOP * H];
__device__ __align__(256) float g_conv[NB * FC1_IN];

// ---------------- init / counting ----------------
__global__ void zero_deg_cnt_k() {
    int i = blockIdx.x * blockDim.x + threadIdx.x;
    if (i < N_NODES) g_deg[i] = 0;
    if (i < NB) g_cnt[i] = 0;
}
__global__ void count_k(const int* __restrict__ dst, const int* __restrict__ batch) {
    int e = blockIdx.x * blockDim.x + threadIdx.x;
    if (e < N_EDGES) atomicAdd(&g_deg[dst[e]], 1);
    if (e < N_NODES) atomicAdd(&g_cnt[batch[e]], 1);
}
__global__ void scan_k() {   // graph starts (batch is sorted)
    __shared__ int s[NB];
    int t = threadIdx.x;
    s[t] = g_cnt[t];
    __syncthreads();
    for (int off = 1; off < NB; off <<= 1) {
        int v = (t >= off) ? s[t - off] : 0;
        __syncthreads();
        s[t] += v;
        __syncthreads();
    }
    g_start[t] = s[t] - g_cnt[t];
}

// ---------------- 3-stage coalesced exclusive scan of g_deg ----------------
__global__ void scanA_k() {
    __shared__ int s[256];
    int b = blockIdx.x, t = threadIdx.x;
    int idx = b * 256 + t;
    int v = (idx < N_NODES) ? g_deg[idx] : 0;
    s[t] = v;
    __syncthreads();
    for (int off = 1; off < 256; off <<= 1) {
        int u = (t >= off) ? s[t - off] : 0;
        __syncthreads();
        s[t] += u;
        __syncthreads();
    }
    if (t == 255) g_bsum[b] = s[255];
}
__global__ void scanB_k() {
    __shared__ int s[256];
    int t = threadIdx.x;
    s[t] = (t < SCB) ? g_bsum[t] : 0;
    __syncthreads();
    for (int off = 1; off < 256; off <<= 1) {
        int u = (t >= off) ? s[t - off] : 0;
        __syncthreads();
        s[t] += u;
        __syncthreads();
    }
    if (t < SCB) g_boff[t] = s[t] - g_bsum[t];
}
__global__ void scanC_k() {
    __shared__ int s[256];
    int b = blockIdx.x, t = threadIdx.x;
    int idx = b * 256 + t;
    int v = (idx < N_NODES) ? g_deg[idx] : 0;
    s[t] = v;
    __syncthreads();
    for (int off = 1; off < 256; off <<= 1) {
        int u = (t >= off) ? s[t - off] : 0;
        __syncthreads();
        s[t] += u;
        __syncthreads();
    }
    if (idx < N_NODES) {
        int ex = g_boff[b] + s[t] - v;
        g_rowstart[idx] = ex;
        g_cursor[idx]   = ex;
    }
}
__global__ void fillcsr_k(const int* __restrict__ src, const int* __restrict__ dst) {
    int e = blockIdx.x * blockDim.x + threadIdx.x;
    if (e < N_EDGES) {
        int pos = atomicAdd(&g_cursor[dst[e]], 1);
        g_csr[pos] = src[e];
    }
}

// ---------------- weight prep ----------------
__global__ void wcat_all_k(const float* __restrict__ W1l, const float* __restrict__ W1r,
                           const float* __restrict__ W2l, const float* __restrict__ W2r,
                           const float* __restrict__ W3l, const float* __restrict__ W3r) {
    int i = blockIdx.x * blockDim.x + threadIdx.x;
    if (i < F0 * 64) {
        int k = i >> 6, j = i & 63;
        g_wcat[0][k * 128 + j]      = W1l[i];
        g_wcat[0][k * 128 + 64 + j] = W1r[i];
    } else if (i < F0 * 64 + H * 64) {
        int p = i - F0 * 64;
        int k = p >> 6, j = p & 63;
        g_wcat[1][k * 128 + j]      = W2l[p];
        g_wcat[1][k * 128 + 64 + j] = W2r[p];
    } else if (i < F0 * 64 + 2 * H * 64) {
        int p = i - F0 * 64 - H * 64;
        int k = p >> 6, j = p & 63;
        g_wcat[2][k * 128 + j]      = W3l[p];
        g_wcat[2][k * 128 + 64 + j] = W3r[p];
    }
}
__global__ void w1t_k(const float* __restrict__ w1) {
    int i = blockIdx.x * blockDim.x + threadIdx.x;  // 0..53247
    if (i < H * FC1_IN) {
        int r = i / FC1_IN, c = i % FC1_IN;
        g_w1t[i] = w1[c * H + r];
    }
}

// ---------------- tiled GEMM (FFMA2): C[M x 128] = A[M x K] @ B[K x 128] --------
template <int K>
__global__ __launch_bounds__(256) void gemm_k(const float* __restrict__ A,
                                              const float* __restrict__ B,
                                              float* __restrict__ C) {
    const int MT = 128, NT = 128, KT = 32;
    __shared__ float sA[MT][KT + 4];   // [m][k]
    __shared__ float sB[KT][NT];       // [k][n]
    int t = threadIdx.x;
    int m0 = blockIdx.x * MT;
    int ty = t >> 4, tx = t & 15;      // 16x16 threads, 8x8 micro-tile
    // accumulators packed along j: acc[i][q] = {c[i][2q], c[i][2q+1]}
    unsigned long long acc[8][4];
#pragma unroll
    for (int i = 0; i < 8; i++)
#pragma unroll
        for (int q = 0; q < 4; q++) acc[i][q] = 0ULL;

    for (int kk = 0; kk < K; kk += KT) {
#pragma unroll
        for (int i = 0; i < 4; i++) {           // A tile: 128 x 32
            int lin = t + i * 256;
            int row = lin >> 3;
            int c4  = lin & 7;
            int grow = m0 + row;
            float4 v = make_float4(0.f, 0.f, 0.f, 0.f);
            if (grow < N_NODES)
                v = *(const float4*)(A + (long long)grow * K + kk + c4 * 4);
            *(float4*)&sA[row][c4 * 4] = v;
        }
#pragma unroll
        for (int i = 0; i < 4; i++) {           // B tile: 32 x 128
            int lin = t + i * 256;
            int row = lin >> 5;
            int c4  = lin & 31;
            *(float4*)&sB[row][c4 * 4] = *(const float4*)(B + (row + kk) * 128 + c4 * 4);
        }
        __syncthreads();
#pragma unroll
        for (int k = 0; k < KT; k++) {
            // b as natural f32x2 pairs (LDS.128 -> aligned reg pairs)
            ulonglong2 bq0 = *(ulonglong2*)&sB[k][tx * 8];
            ulonglong2 bq1 = *(ulonglong2*)&sB[k][tx * 8 + 4];
#pragma unroll
            for (int i = 0; i < 8; i++) {
                unsigned int au = __float_as_uint(sA[ty * 8 + i][k]);
                unsigned long long ab;
                asm("mov.b64 %0, {%1, %1};" : "=l"(ab) : "r"(au));
                asm("fma.rn.f32x2 %0, %1, %2, %0;" : "+l"(acc[i][0]) : "l"(ab), "l"(bq0.x));
                asm("fma.rn.f32x2 %0, %1, %2, %0;" : "+l"(acc[i][1]) : "l"(ab), "l"(bq0.y));
                asm("fma.rn.f32x2 %0, %1, %2, %0;" : "+l"(acc[i][2]) : "l"(ab), "l"(bq1.x));
                asm("fma.rn.f32x2 %0, %1, %2, %0;" : "+l"(acc[i][3]) : "l"(ab), "l"(bq1.y));
            }
        }
        __syncthreads();
    }
#pragma unroll
    for (int i = 0; i < 8; i++) {
        int grow = m0 + ty * 8 + i;
        if (grow < N_NODES) {
            ulonglong2 v0, v1;
            v0.x = acc[i][0]; v0.y = acc[i][1];
            v1.x = acc[i][2]; v1.y = acc[i][3];
            *(ulonglong2*)(C + (long long)grow * 128 + tx * 8)     = v0;
            *(ulonglong2*)(C + (long long)grow * 128 + tx * 8 + 4) = v1;
        }
    }
}

// ---------------- gather: out = relu( mean_{j in N(i)} C[j,:64] + C[i,64:] + b ) ----
__global__ void gather_k(const float4* __restrict__ C4, const float* __restrict__ bias,
                         float* __restrict__ out) {
    int node = blockIdx.x * 8 + (threadIdx.x >> 4);
    if (node >= N_NODES) return;
    int l = threadIdx.x & 15;
    int s = g_rowstart[node];
    int d = g_deg[node];
    float4 acc = make_float4(0.f, 0.f, 0.f, 0.f);
    int e = 0;
    for (; e + 4 <= d; e += 4) {
        int j0 = g_csr[s + e];
        int j1 = g_csr[s + e + 1];
        int j2 = g_csr[s + e + 2];
        int j3 = g_csr[s + e + 3];
        float4 a = C4[(long long)j0 * 32 + l];
        float4 b = C4[(long long)j1 * 32 + l];
        float4 c = C4[(long long)j2 * 32 + l];
        float4 dd = C4[(long long)j3 * 32 + l];
        acc.x += a.x + b.x + c.x + dd.x;
        acc.y += a.y + b.y + c.y + dd.y;
        acc.z += a.z + b.z + c.z + dd.z;
        acc.w += a.w + b.w + c.w + dd.w;
    }
    for (; e < d; e++) {
        float4 a = C4[(long long)g_csr[s + e] * 32 + l];
        acc.x += a.x; acc.y += a.y; acc.z += a.z; acc.w += a.w;
    }
    float dinv = 1.f / fmaxf((float)d, 1.f);
    float4 self = C4[(long long)node * 32 + 16 + l];
    float4 bv = ((const float4*)bias)[l];
    float4 r;
    r.x = fmaxf(acc.x * dinv + self.x + bv.x, 0.f);
    r.y = fmaxf(acc.y * dinv + self.y + bv.y, 0.f);
    r.z = fmaxf(acc.z * dinv + self.z + bv.z, 0.f);
    r.w = fmaxf(acc.w * dinv + self.w + bv.w, 0.f);
    ((float4*)out)[(long long)node * 16 + l] = r;
}

// ---------------- sort-pool: stable top-K by last channel desc (zero-pad fused) ----
__global__ void sortpool_k(const float* __restrict__ h) {
    int g = blockIdx.x;
    int tid = threadIdx.x;
    int s0 = g_start[g], n = g_cnt[g];
    __shared__ float v[MAXN];
    __shared__ int sel[KTOP];
    bool fits = (n <= MAXN);
    if (fits)
        for (int i = tid; i < n; i += blockDim.x)
            v[i] = h[(long long)(s0 + i) * H + (H - 1)];
    __syncthreads();
    for (int i = tid; i < n; i += blockDim.x) {
        float vi = fits ? v[i] : h[(long long)(s0 + i) * H + (H - 1)];
        int r = 0;
        for (int j = 0; j < n; j++) {
            float vj = fits ? v[j] : h[(long long)(s0 + j) * H + (H - 1)];
            r += (vj > vi) || (vj == vi && j < i);
            if (r >= KTOP) break;
        }
        if (r < KTOP) sel[r] = s0 + i;
    }
    __syncthreads();
    int m = n < KTOP ? n : KTOP;
    for (int idx = tid; idx < KTOP * H; idx += blockDim.x) {
        int r = idx >> 6, c = idx & 63;
        float val = (r < m) ? h[(long long)sel[r] * H + c] : 0.f;
        g_pool[((long long)g * KTOP + r) * H + c] = val;
    }
}

// ---------------- conv1d (NCH, OIH, VALID, kernel=5) + relu ----------------
__global__ void conv_k(const float* __restrict__ convw,
                       const float* __restrict__ convb) {
    int g = blockIdx.x;
    int tid = threadIdx.x;
    __shared__ float p[KTOP * H];
    __shared__ float sw[CCH * 321];
    for (int i = tid; i < KTOP * H; i += blockDim.x)
        p[i] = g_pool[(long long)g * KTOP * H + i];
    for (int i = tid; i < CCH * 320; i += blockDim.x) {
        int o = i / 320, c = i % 320;
        sw[o * 321 + c] = convw[i];
    }
    __syncthreads();
    for (int idx = tid; idx < CCH * LOUT; idx += blockDim.x) {
        int o = idx & 31;
        int t = idx >> 5;
        float acc = convb[o];
        const float* w = sw + o * 321;
#pragma unroll 4
        for (int i = 0; i < H; i++) {
#pragma unroll
            for (int hh = 0; hh < 5; hh++)
                acc = fmaf(p[(t + hh) * H + i], w[i * 5 + hh], acc);
        }
        g_conv[(long long)g * FC1_IN + o * LOUT + t] = fmaxf(acc, 0.f);
    }
}

// ---------------- FC1 + relu, FC2, log_softmax ----------------
__global__ void fc_k(const float* __restrict__ b1v,
                     const float* __restrict__ w2, const float* __restrict__ b2v,
                     float* __restrict__ out) {
    int g = blockIdx.x;
    int t = threadIdx.x;                   // 64 threads
    __shared__ float4 c4s[FC1_IN / 4];     // 208
    __shared__ float f[H];
    __shared__ float logits[10];
    const float4* cg = (const float4*)(g_conv + (long long)g * FC1_IN);
    for (int i = t; i < FC1_IN / 4; i += H) c4s[i] = cg[i];
    __syncthreads();
    float acc = b1v[t];
    const float4* wr = (const float4*)(g_w1t + (long long)t * FC1_IN);
#pragma unroll 4
    for (int k = 0; k < FC1_IN / 4; k++) {
        float4 cv = c4s[k];
        float4 wv = wr[k];
        acc = fmaf(cv.x, wv.x, acc);
        acc = fmaf(cv.y, wv.y, acc);
        acc = fmaf(cv.z, wv.z, acc);
        acc = fmaf(cv.w, wv.w, acc);
    }
    f[t] = fmaxf(acc, 0.f);
    __syncthreads();
    if (t < 10) {
        float a = b2v[t];
#pragma unroll
        for (int k = 0; k < H; k++) a = fmaf(f[k], w2[k * 10 + t], a);
        logits[t] = a;
    }
    __syncthreads();
    if (t == 0) {
        float mx = -1e30f;
        for (int i = 0; i < 10; i++) mx = fmaxf(mx, logits[i]);
        float s = 0.f;
        for (int i = 0; i < 10; i++) s += expf(logits[i] - mx);
        float ls = logf(s) + mx;
        for (int i = 0; i < 10; i++) out[g * 10 + i] = logits[i] - ls;
    }
}

extern "C" void kernel_launch(void* const* d_in, const int* in_sizes, int n_in,
                              void* d_out, int out_size) {
    const float* x     = (const float*)d_in[0];
    const int*   ei    = (const int*)d_in[1];      // int32 (JAX x64 disabled)
    const int*   batch = (const int*)d_in[2];      // int32
    const float* W1l = (const float*)d_in[3];
    const float* b1  = (const float*)d_in[4];
    const float* W1r = (const float*)d_in[5];
    const float* W2l = (const float*)d_in[6];
    const float* b2  = (const float*)d_in[7];
    const float* W2r = (const float*)d_in[8];
    const float* W3l = (const float*)d_in[9];
    const float* b3  = (const float*)d_in[10];
    const float* W3r = (const float*)d_in[11];
    const float* convw = (const float*)d_in[12];
    const float* convb = (const float*)d_in[13];
    const float* lin1w = (const float*)d_in[14];
    const float* lin1b = (const float*)d_in[15];
    const float* lin2w = (const float*)d_in[16];
    const float* lin2b = (const float*)d_in[17];
    const int* src = ei;
    const int* dst = ei + N_EDGES;
    float* out = (float*)d_out;

    float* wc0;  cudaGetSymbolAddress((void**)&wc0, g_wcat);
    float* wc1 = wc0 + F0 * 128;
    float* wc2 = wc0 + 2 * F0 * 128;
    float* Cbuf; cudaGetSymbolAddress((void**)&Cbuf, g_C);
    float* h1;   cudaGetSymbolAddress((void**)&h1, g_h1);
    float* h2;   cudaGetSymbolAddress((void**)&h2, g_h2);

    const int GB = (N_NODES + 127) / 128;
    const int AB = (N_NODES + 7) / 8;

    // index 0..2
    zero_deg_cnt_k<<<(N_NODES + 255) / 256, 256>>>();
    count_k<<<(N_EDGES + 255) / 256, 256>>>(dst, batch);
    wcat_all_k<<<(F0 * 64 + 2 * H * 64 + 255) / 256, 256>>>(W1l, W1r, W2l, W2r, W3l, W3r);

    // index 3: profiled slot — layer-1 GEMM (FFMA2)
    gemm_k<F0><<<GB, 256>>>(x, wc0, Cbuf);

    // CSR build + graph offsets + FC weight transpose
    scan_k<<<1, NB>>>();
    scanA_k<<<SCB, 256>>>();
    scanB_k<<<1, 256>>>();
    scanC_k<<<SCB, 256>>>();
    fillcsr_k<<<(N_EDGES + 255) / 256, 256>>>(src, dst);
    w1t_k<<<(H * FC1_IN + 255) / 256, 256>>>(lin1w);

    // layers
    gather_k<<<AB, 128>>>((const float4*)Cbuf, b1, h1);
    gemm_k<H><<<GB, 256>>>(h1, wc1, Cbuf);
    gather_k<<<AB, 128>>>((const float4*)Cbuf, b2, h2);
    gemm_k<H><<<GB, 256>>>(h2, wc2, Cbuf);
    gather_k<<<AB, 128>>>((const float4*)Cbuf, b3, h1);

    // sort-pool + conv + mlp + log_softmax
    sortpool_k<<<NB, 128>>>(h1);
    conv_k<<<NB, 256>>>(convw, convb);
    fc_k<<<NB, H>>>(lin1b, lin2w, lin2b, out);
}

// round 13
// speedup vs baseline: 12.9709x; 1.0269x over previous
#include <cuda_runtime.h>
#include <cuda_bf16.h>

#define N_NODES 50000
#define N_EDGES 800000
#define F0      128
#define H       64
#define NB      512
#define KTOP    30
#define CCH     32
#define LOUT    26      // KTOP - 5 + 1
#define FC1_IN  832     // 32*26
#define MAXN    1024
#define SCB     196     // scan blocks: 196*256 >= 50000

// ---------------- scratch (device globals; no allocation) ----------------
__device__ __align__(256) float g_C[N_NODES * 128];     // GEMM out: [ h@Wl | h@Wr ]
__device__ __align__(256) float g_h1[N_NODES * H];
__device__ __align__(256) float g_h2[N_NODES * H];
__device__ __align__(256) float g_wcat[3][F0 * 128];    // per-layer [Wl|Wr], K-major
__device__ __align__(256) float g_w1t[H * FC1_IN];      // lin1w transposed [64][832]
__device__ int   g_deg[N_NODES];
__device__ int   g_rowstart[N_NODES];
__device__ int   g_cursor[N_NODES];
__device__ int   g_csr[N_EDGES];
__device__ int   g_cnt[NB];
__device__ int   g_start[NB];
__device__ int   g_bsum[SCB];
__device__ int   g_boff[SCB];
__device__ __align__(256) float g_pool[NB * KTOP * H];
__device__ __align__(256) float g_conv[NB * FC1_IN];

// ---------------- init / counting ----------------
__global__ void zero_deg_cnt_k() {
    int i = blockIdx.x * blockDim.x + threadIdx.x;
    if (i < N_NODES) g_deg[i] = 0;
    if (i < NB) g_cnt[i] = 0;
}
__global__ void count_k(const int* __restrict__ dst, const int* __restrict__ batch) {
    int e = blockIdx.x * blockDim.x + threadIdx.x;
    if (e < N_EDGES) atomicAdd(&g_deg[dst[e]], 1);
    if (e < N_NODES) atomicAdd(&g_cnt[batch[e]], 1);
}

// ---------------- scans ----------------
__global__ void scanA_k() {            // per-block sums of g_deg
    __shared__ int s[256];
    int b = blockIdx.x, t = threadIdx.x;
    int idx = b * 256 + t;
    int v = (idx < N_NODES) ? g_deg[idx] : 0;
    s[t] = v;
    __syncthreads();
    for (int off = 1; off < 256; off <<= 1) {
        int u = (t >= off) ? s[t - off] : 0;
        __syncthreads();
        s[t] += u;
        __syncthreads();
    }
    if (t == 255) g_bsum[b] = s[255];
}
// block 0: scan SCB block sums -> g_boff ; block 1: graph starts from g_cnt
__global__ void scanB_k() {
    __shared__ int s[NB];
    int t = threadIdx.x;
    if (blockIdx.x == 0) {
        if (t < 256) {
            s[t] = (t < SCB) ? g_bsum[t] : 0;
        }
        __syncthreads();
        for (int off = 1; off < 256; off <<= 1) {
            int u = (t >= off && t < 256) ? s[t - off] : 0;
            __syncthreads();
            if (t < 256) s[t] += u;
            __syncthreads();
        }
        if (t < SCB) g_boff[t] = s[t] - g_bsum[t];
    } else {
        s[t] = g_cnt[t];
        __syncthreads();
        for (int off = 1; off < NB; off <<= 1) {
            int v = (t >= off) ? s[t - off] : 0;
            __syncthreads();
            s[t] += v;
            __syncthreads();
        }
        g_start[t] = s[t] - g_cnt[t];
    }
}
__global__ void scanC_k() {            // finalize rowstart / cursor
    __shared__ int s[256];
    int b = blockIdx.x, t = threadIdx.x;
    int idx = b * 256 + t;
    int v = (idx < N_NODES) ? g_deg[idx] : 0;
    s[t] = v;
    __syncthreads();
    for (int off = 1; off < 256; off <<= 1) {
        int u = (t >= off) ? s[t - off] : 0;
        __syncthreads();
        s[t] += u;
        __syncthreads();
    }
    if (idx < N_NODES) {
        int ex = g_boff[b] + s[t] - v;
        g_rowstart[idx] = ex;
        g_cursor[idx]   = ex;
    }
}
__global__ void fillcsr_k(const int* __restrict__ src, const int* __restrict__ dst) {
    int e = blockIdx.x * blockDim.x + threadIdx.x;
    if (e < N_EDGES) {
        int pos = atomicAdd(&g_cursor[dst[e]], 1);
        g_csr[pos] = src[e];
    }
}

// ---------------- weight prep ----------------
__global__ void wcat_all_k(const float* __restrict__ W1l, const float* __restrict__ W1r,
                           const float* __restrict__ W2l, const float* __restrict__ W2r,
                           const float* __restrict__ W3l, const float* __restrict__ W3r) {
    int i = blockIdx.x * blockDim.x + threadIdx.x;
    if (i < F0 * 64) {
        int k = i >> 6, j = i & 63;
        g_wcat[0][k * 128 + j]      = W1l[i];
        g_wcat[0][k * 128 + 64 + j] = W1r[i];
    } else if (i < F0 * 64 + H * 64) {
        int p = i - F0 * 64;
        int k = p >> 6, j = p & 63;
        g_wcat[1][k * 128 + j]      = W2l[p];
        g_wcat[1][k * 128 + 64 + j] = W2r[p];
    } else if (i < F0 * 64 + 2 * H * 64) {
        int p = i - F0 * 64 - H * 64;
        int k = p >> 6, j = p & 63;
        g_wcat[2][k * 128 + j]      = W3l[p];
        g_wcat[2][k * 128 + 64 + j] = W3r[p];
    }
}
__global__ void w1t_k(const float* __restrict__ w1) {
    int i = blockIdx.x * blockDim.x + threadIdx.x;  // 0..53247
    if (i < H * FC1_IN) {
        int r = i / FC1_IN, c = i % FC1_IN;
        g_w1t[i] = w1[c * H + r];
    }
}

// ---------------- tiled GEMM (FFMA2, 2 CTA/SM): C[M x 128] = A[M x K] @ B[K x 128]
template <int K>
__global__ __launch_bounds__(256, 2) void gemm_k(const float* __restrict__ A,
                                                 const float* __restrict__ B,
                                                 float* __restrict__ C) {
    const int MT = 128, NT = 128, KT = 32;
    __shared__ float sA[MT][KT + 4];   // [m][k]
    __shared__ float sB[KT][NT];       // [k][n]
    int t = threadIdx.x;
    int m0 = blockIdx.x * MT;
    int ty = t >> 4, tx = t & 15;      // 16x16 threads, 8x8 micro-tile
    // accumulators packed along j: acc[i][q] = {c[i][2q], c[i][2q+1]}
    unsigned long long acc[8][4];
#pragma unroll
    for (int i = 0; i < 8; i++)
#pragma unroll
        for (int q = 0; q < 4; q++) acc[i][q] = 0ULL;

    for (int kk = 0; kk < K; kk += KT) {
#pragma unroll
        for (int i = 0; i < 4; i++) {           // A tile: 128 x 32
            int lin = t + i * 256;
            int row = lin >> 3;
            int c4  = lin & 7;
            int grow = m0 + row;
            float4 v = make_float4(0.f, 0.f, 0.f, 0.f);
            if (grow < N_NODES)
                v = *(const float4*)(A + (long long)grow * K + kk + c4 * 4);
            *(float4*)&sA[row][c4 * 4] = v;
        }
#pragma unroll
        for (int i = 0; i < 4; i++) {           // B tile: 32 x 128
            int lin = t + i * 256;
            int row = lin >> 5;
            int c4  = lin & 31;
            *(float4*)&sB[row][c4 * 4] = *(const float4*)(B + (row + kk) * 128 + c4 * 4);
        }
        __syncthreads();
#pragma unroll
        for (int k = 0; k < KT; k++) {
            ulonglong2 bq0 = *(ulonglong2*)&sB[k][tx * 8];
            ulonglong2 bq1 = *(ulonglong2*)&sB[k][tx * 8 + 4];
#pragma unroll
            for (int i = 0; i < 8; i++) {
                unsigned int au = __float_as_uint(sA[ty * 8 + i][k]);
                unsigned long long ab;
                asm("mov.b64 %0, {%1, %1};" : "=l"(ab) : "r"(au));
                asm("fma.rn.f32x2 %0, %1, %2, %0;" : "+l"(acc[i][0]) : "l"(ab), "l"(bq0.x));
                asm("fma.rn.f32x2 %0, %1, %2, %0;" : "+l"(acc[i][1]) : "l"(ab), "l"(bq0.y));
                asm("fma.rn.f32x2 %0, %1, %2, %0;" : "+l"(acc[i][2]) : "l"(ab), "l"(bq1.x));
                asm("fma.rn.f32x2 %0, %1, %2, %0;" : "+l"(acc[i][3]) : "l"(ab), "l"(bq1.y));
            }
        }
        __syncthreads();
    }
#pragma unroll
    for (int i = 0; i < 8; i++) {
        int grow = m0 + ty * 8 + i;
        if (grow < N_NODES) {
            ulonglong2 v0, v1;
            v0.x = acc[i][0]; v0.y = acc[i][1];
            v1.x = acc[i][2]; v1.y = acc[i][3];
            *(ulonglong2*)(C + (long long)grow * 128 + tx * 8)     = v0;
            *(ulonglong2*)(C + (long long)grow * 128 + tx * 8 + 4) = v1;
        }
    }
}

// ---------------- gather: out = relu( mean_{j in N(i)} C[j,:64] + C[i,64:] + b ) ----
__global__ void gather_k(const float4* __restrict__ C4, const float* __restrict__ bias,
                         float* __restrict__ out) {
    int node = blockIdx.x * 8 + (threadIdx.x >> 4);
    if (node >= N_NODES) return;
    int l = threadIdx.x & 15;
    int s = g_rowstart[node];
    int d = g_deg[node];
    float4 acc = make_float4(0.f, 0.f, 0.f, 0.f);
    int e = 0;
    for (; e + 4 <= d; e += 4) {
        int j0 = g_csr[s + e];
        int j1 = g_csr[s + e + 1];
        int j2 = g_csr[s + e + 2];
        int j3 = g_csr[s + e + 3];
        float4 a = C4[(long long)j0 * 32 + l];
        float4 b = C4[(long long)j1 * 32 + l];
        float4 c = C4[(long long)j2 * 32 + l];
        float4 dd = C4[(long long)j3 * 32 + l];
        acc.x += a.x + b.x + c.x + dd.x;
        acc.y += a.y + b.y + c.y + dd.y;
        acc.z += a.z + b.z + c.z + dd.z;
        acc.w += a.w + b.w + c.w + dd.w;
    }
    for (; e < d; e++) {
        float4 a = C4[(long long)g_csr[s + e] * 32 + l];
        acc.x += a.x; acc.y += a.y; acc.z += a.z; acc.w += a.w;
    }
    float dinv = 1.f / fmaxf((float)d, 1.f);
    float4 self = C4[(long long)node * 32 + 16 + l];
    float4 bv = ((const float4*)bias)[l];
    float4 r;
    r.x = fmaxf(acc.x * dinv + self.x + bv.x, 0.f);
    r.y = fmaxf(acc.y * dinv + self.y + bv.y, 0.f);
    r.z = fmaxf(acc.z * dinv + self.z + bv.z, 0.f);
    r.w = fmaxf(acc.w * dinv + self.w + bv.w, 0.f);
    ((float4*)out)[(long long)node * 16 + l] = r;
}

// ---------------- sort-pool: stable top-K by last channel desc (zero-pad fused) ----
__global__ void sortpool_k(const float* __restrict__ h) {
    int g = blockIdx.x;
    int tid = threadIdx.x;
    int s0 = g_start[g], n = g_cnt[g];
    __shared__ float v[MAXN];
    __shared__ int sel[KTOP];
    bool fits = (n <= MAXN);
    if (fits)
        for (int i = tid; i < n; i += blockDim.x)
            v[i] = h[(long long)(s0 + i) * H + (H - 1)];
    __syncthreads();
    for (int i = tid; i < n; i += blockDim.x) {
        float vi = fits ? v[i] : h[(long long)(s0 + i) * H + (H - 1)];
        int r = 0;
        for (int j = 0; j < n; j++) {
            float vj = fits ? v[j] : h[(long long)(s0 + j) * H + (H - 1)];
            r += (vj > vi) || (vj == vi && j < i);
            if (r >= KTOP) break;
        }
        if (r < KTOP) sel[r] = s0 + i;
    }
    __syncthreads();
    int m = n < KTOP ? n : KTOP;
    for (int idx = tid; idx < KTOP * H; idx += blockDim.x) {
        int r = idx >> 6, c = idx & 63;
        float val = (r < m) ? h[(long long)sel[r] * H + c] : 0.f;
        g_pool[((long long)g * KTOP + r) * H + c] = val;
    }
}

// ---------------- conv1d (NCH, OIH, VALID, kernel=5) + relu ----------------
__global__ void conv_k(const float* __restrict__ convw,
                       const float* __restrict__ convb) {
    int g = blockIdx.x;
    int tid = threadIdx.x;
    __shared__ float p[KTOP * H];
    __shared__ float sw[CCH * 321];
    for (int i = tid; i < KTOP * H; i += blockDim.x)
        p[i] = g_pool[(long long)g * KTOP * H + i];
    for (int i = tid; i < CCH * 320; i += blockDim.x) {
        int o = i / 320, c = i % 320;
        sw[o * 321 + c] = convw[i];
    }
    __syncthreads();
    for (int idx = tid; idx < CCH * LOUT; idx += blockDim.x) {
        int o = idx & 31;
        int t = idx >> 5;
        float acc = convb[o];
        const float* w = sw + o * 321;
#pragma unroll 4
        for (int i = 0; i < H; i++) {
#pragma unroll
            for (int hh = 0; hh < 5; hh++)
                acc = fmaf(p[(t + hh) * H + i], w[i * 5 + hh], acc);
        }
        g_conv[(long long)g * FC1_IN + o * LOUT + t] = fmaxf(acc, 0.f);
    }
}

// ---------------- FC1 + relu, FC2, log_softmax ----------------
__global__ void fc_k(const float* __restrict__ b1v,
                     const float* __restrict__ w2, const float* __restrict__ b2v,
                     float* __restrict__ out) {
    int g = blockIdx.x;
    int t = threadIdx.x;                   // 64 threads
    __shared__ float4 c4s[FC1_IN / 4];     // 208
    __shared__ float f[H];
    __shared__ float logits[10];
    const float4* cg = (const float4*)(g_conv + (long long)g * FC1_IN);
    for (int i = t; i < FC1_IN / 4; i += H) c4s[i] = cg[i];
    __syncthreads();
    float acc = b1v[t];
    const float4* wr = (const float4*)(g_w1t + (long long)t * FC1_IN);
#pragma unroll 4
    for (int k = 0; k < FC1_IN / 4; k++) {
        float4 cv = c4s[k];
        float4 wv = wr[k];
        acc = fmaf(cv.x, wv.x, acc);
        acc = fmaf(cv.y, wv.y, acc);
        acc = fmaf(cv.z, wv.z, acc);
        acc = fmaf(cv.w, wv.w, acc);
    }
    f[t] = fmaxf(acc, 0.f);
    __syncthreads();
    if (t < 10) {
        float a = b2v[t];
#pragma unroll
        for (int k = 0; k < H; k++) a = fmaf(f[k], w2[k * 10 + t], a);
        logits[t] = a;
    }
    __syncthreads();
    if (t == 0) {
        float mx = -1e30f;
        for (int i = 0; i < 10; i++) mx = fmaxf(mx, logits[i]);
        float s = 0.f;
        for (int i = 0; i < 10; i++) s += expf(logits[i] - mx);
        float ls = logf(s) + mx;
        for (int i = 0; i < 10; i++) out[g * 10 + i] = logits[i] - ls;
    }
}

extern "C" void kernel_launch(void* const* d_in, const int* in_sizes, int n_in,
                              void* d_out, int out_size) {
    const float* x     = (const float*)d_in[0];
    const int*   ei    = (const int*)d_in[1];      // int32 (JAX x64 disabled)
    const int*   batch = (const int*)d_in[2];      // int32
    const float* W1l = (const float*)d_in[3];
    const float* b1  = (const float*)d_in[4];
    const float* W1r = (const float*)d_in[5];
    const float* W2l = (const float*)d_in[6];
    const float* b2  = (const float*)d_in[7];
    const float* W2r = (const float*)d_in[8];
    const float* W3l = (const float*)d_in[9];
    const float* b3  = (const float*)d_in[10];
    const float* W3r = (const float*)d_in[11];
    const float* convw = (const float*)d_in[12];
    const float* convb = (const float*)d_in[13];
    const float* lin1w = (const float*)d_in[14];
    const float* lin1b = (const float*)d_in[15];
    const float* lin2w = (const float*)d_in[16];
    const float* lin2b = (const float*)d_in[17];
    const int* src = ei;
    const int* dst = ei + N_EDGES;
    float* out = (float*)d_out;

    float* wc0;  cudaGetSymbolAddress((void**)&wc0, g_wcat);
    float* wc1 = wc0 + F0 * 128;
    float* wc2 = wc0 + 2 * F0 * 128;
    float* Cbuf; cudaGetSymbolAddress((void**)&Cbuf, g_C);
    float* h1;   cudaGetSymbolAddress((void**)&h1, g_h1);
    float* h2;   cudaGetSymbolAddress((void**)&h2, g_h2);

    const int GB = (N_NODES + 127) / 128;
    const int AB = (N_NODES + 7) / 8;

    // index 0..2
    zero_deg_cnt_k<<<(N_NODES + 255) / 256, 256>>>();
    count_k<<<(N_EDGES + 255) / 256, 256>>>(dst, batch);
    wcat_all_k<<<(F0 * 64 + 2 * H * 64 + 255) / 256, 256>>>(W1l, W1r, W2l, W2r, W3l, W3r);

    // index 3: profiled slot — layer-1 GEMM (FFMA2, 2 CTA/SM)
    gemm_k<F0><<<GB, 256>>>(x, wc0, Cbuf);

    // CSR build + graph offsets + FC weight transpose
    scanA_k<<<SCB, 256>>>();
    scanB_k<<<2, NB>>>();              // block0: deg block-sum scan; block1: graph starts
    scanC_k<<<SCB, 256>>>();
    fillcsr_k<<<(N_EDGES + 255) / 256, 256>>>(src, dst);
    w1t_k<<<(H * FC1_IN + 255) / 256, 256>>>(lin1w);

    // layers
    gather_k<<<AB, 128>>>((const float4*)Cbuf, b1, h1);
    gemm_k<H><<<GB, 256>>>(h1, wc1, Cbuf);
    gather_k<<<AB, 128>>>((const float4*)Cbuf, b2, h2);
    gemm_k<H><<<GB, 256>>>(h2, wc2, Cbuf);
    gather_k<<<AB, 128>>>((const float4*)Cbuf, b3, h1);

    // sort-pool + conv + mlp + log_softmax
    sortpool_k<<<NB, 128>>>(h1);
    conv_k<<<NB, 256>>>(convw, convb);
    fc_k<<<NB, H>>>(lin1b, lin2w, lin2b, out);
}